// round 4
// baseline (speedup 1.0000x reference)
#include <cuda_runtime.h>
#include <cstdint>

#define Bsz 256
#define Tlen 512
#define HH 100
#define G4 400
#define Oout 3
#define CL 16          // steps per chunk
#define NCHK 32        // chunks (Tlen/CL)

typedef unsigned long long ull;

#define FMA2(d, a, b, c) asm("fma.rn.f32x2 %0, %1, %2, %3;" : "=l"(d) : "l"(a), "l"(b), "l"(c))
#define PACK2(d, lo, hi) asm("mov.b64 %0, {%1, %2};" : "=l"(d) : "f"(lo), "f"(hi))
#define UNPACK2(lo, hi, v) asm("mov.b64 {%0, %1}, %2;" : "=f"(lo), "=f"(hi) : "l"(v))

// ---------------------------------------------------------------------------
// Device globals
// ---------------------------------------------------------------------------
__device__ float g_h[(size_t)4 * Bsz * Tlen * HH];   // layers 0..3 hidden seqs
__device__ float g_hLast[Bsz * HH];                  // layer 4, t=T-1
__device__ unsigned g_flag[4][32];                   // chunk progress (monotonic)
__device__ unsigned g_epoch[160];                    // per-block launch counter

__device__ __forceinline__ float sigf(float x) {
    return __fdividef(1.0f, 1.0f + __expf(-x));
}
__device__ __forceinline__ float tanh_(float x) {
    return __fdividef(2.0f, 1.0f + __expf(-2.0f * x)) - 1.0f;
}

__device__ __forceinline__ void flag_release(unsigned* p, unsigned v) {
    asm volatile("st.release.gpu.global.u32 [%0], %1;" :: "l"(p), "r"(v) : "memory");
}
__device__ __forceinline__ void flag_spin(unsigned* p, unsigned target) {
    unsigned v;
    while (true) {
        asm volatile("ld.acquire.gpu.global.u32 %0, [%1];" : "=r"(v) : "l"(p) : "memory");
        if ((int)(v - target) >= 0) break;
        __nanosleep(128);
    }
}

// ---------------------------------------------------------------------------
// Shared memory layout (floats)
// ---------------------------------------------------------------------------
#define WIH_P 104                         // padded row stride for W_ih
#define SM_WIH   0                        // 400*104 = 41600
#define SM_HPREV 41600                    // 2 x 800 double buffer
#define SM_HOWN  43200                    // up to 1600 (nr=16)
#define SM_GSH   44800                    // up to 16*400 = 6400
#define SM_TOTF  51200
#define SMEM_BYTES (SM_TOTF * 4)          // 204800 B

// ---------------------------------------------------------------------------
// Persistent chunked-wavefront LSTM: all 5 layers concurrent, skewed 1 chunk.
//   blocks 0..15   : layer 0 (16 rows each)
//   blocks 16..143 : layers 1..4 (32 blocks x 8 rows)
// Per step: ONE merged dot (W_hh regs + W_ih smem) -> gsh; activation.
// Cross-block sync only at chunk boundaries (release/acquire flags).
// ---------------------------------------------------------------------------
__global__ __launch_bounds__(416, 1)
void lstm_wave(const float* __restrict__ x,      // [256,512,5]
               const float* __restrict__ W_ih0,  // [400,5]
               const float* __restrict__ W_hh0,  // [400,100]
               const float* __restrict__ b0,     // [400]
               const float* __restrict__ W_ih,   // [4,400,100]
               const float* __restrict__ W_hh,   // [4,400,100]
               const float* __restrict__ bb)     // [4,400]
{
    extern __shared__ float sm[];
    float* Wihs = sm + SM_WIH;
    float* hown = sm + SM_HOWN;
    float* gsh  = sm + SM_GSH;
    __shared__ unsigned s_base;

    const int tid = threadIdx.x;
    const int bid = blockIdx.x;

    int layer, pb, row0, nr;
    if (bid < 16) { layer = 0; pb = bid;              row0 = bid * 16; nr = 16; }
    else          { layer = 1 + (bid - 16) / 32; pb = (bid - 16) % 32; row0 = pb * 8; nr = 8; }
    const int psrc = (layer == 1) ? (pb >> 1) : pb;

    if (tid == 0) {
        unsigned e = g_epoch[bid] + 1u;
        g_epoch[bid] = e;
        s_base = (e - 1u) * (unsigned)NCHK;
    }

    // W_hh row -> registers (k-pair packed), bias, layer-0 input weights
    ull w2[50];
    float bg = 0.f;
    float w0[5] = {0, 0, 0, 0, 0};
    const float* whh_l = (layer == 0) ? W_hh0 : (W_hh + (size_t)(layer - 1) * G4 * HH);
    if (tid < G4) {
        const float4* wr = (const float4*)(whh_l + (size_t)tid * HH);
#pragma unroll
        for (int j = 0; j < 25; j++) {
            float4 v = wr[j];
            PACK2(w2[2 * j],     v.x, v.y);
            PACK2(w2[2 * j + 1], v.z, v.w);
        }
        bg = (layer == 0) ? b0[tid] : bb[(size_t)(layer - 1) * G4 + tid];
        if (layer == 0) {
#pragma unroll
            for (int k = 0; k < 5; k++) w0[k] = W_ih0[tid * 5 + k];
        }
    }
    // W_ih -> smem, padded rows (layers 1..4)
    if (layer > 0) {
        const float4* Wg = (const float4*)(W_ih + (size_t)(layer - 1) * G4 * HH);
        for (int i = tid; i < G4 * 25; i += 416) {
            int r = i / 25, c4 = i - r * 25;
            *(float4*)&Wihs[r * WIH_P + 4 * c4] = Wg[i];
        }
    }
    for (int i = tid; i < nr * HH; i += 416) hown[i] = 0.f;
    float cst[4] = {0, 0, 0, 0};
    __syncthreads();
    const unsigned fbase = s_base;

    const float* hsrcB = g_h + ((size_t)(layer - 1) * Bsz + row0) * Tlen * HH;
    float* hdstB = g_h + ((size_t)layer * Bsz + row0) * Tlen * HH;
    const int nswp = nr / 4;

    float4 v4 = make_float4(0, 0, 0, 0);
    float xv = 0.f;
    const int pr = tid / 25, pp = (tid - pr * 25) * 4;   // consumer prefetch idx
    const int xr = tid / 5,  xk = tid - (tid / 5) * 5;   // layer-0 prefetch idx

    for (int ck = 0; ck < NCHK; ck++) {
        if (layer > 0 && tid == 0)
            flag_spin(&g_flag[layer - 1][psrc], fbase + (unsigned)ck + 1u);
        __syncthreads();

        const int t0 = ck * CL;
        // prefetch first step of chunk
        if (layer > 0) {
            if (tid < 200) v4 = *(const float4*)(hsrcB + (size_t)pr * Tlen * HH + (size_t)t0 * HH + pp);
        } else {
            if (tid < 80) xv = x[((size_t)(row0 + xr) * Tlen + t0) * 5 + xk];
        }

        for (int tt = 0; tt < CL; tt++) {
            const int t = t0 + tt;
            float* hpv = sm + SM_HPREV + (tt & 1) * 800;

            // stage this step's inputs
            if (layer > 0) { if (tid < 200) *(float4*)&hpv[pr * 100 + pp] = v4; }
            else           { if (tid < 80)  hpv[tid] = xv; }
            __syncthreads();                                     // B1

            // prefetch next step (in flight under the dot)
            if (tt < CL - 1) {
                if (layer > 0) {
                    if (tid < 200) v4 = *(const float4*)(hsrcB + (size_t)pr * Tlen * HH + (size_t)(t + 1) * HH + pp);
                } else {
                    if (tid < 80) xv = x[((size_t)(row0 + xr) * Tlen + t + 1) * 5 + xk];
                }
            }

            // merged dot: gate = bias + Whh(regs)*hown + Wih(smem)*hprev
            if (tid < G4) {
                if (layer > 0) {
                    const ulonglong2* wip = (const ulonglong2*)&Wihs[tid * WIH_P];
                    for (int s = 0; s < nswp; s++) {
                        ull a[4], b[4];
#pragma unroll
                        for (int r = 0; r < 4; r++) { PACK2(a[r], bg, 0.f); PACK2(b[r], 0.f, 0.f); }
                        const ulonglong2* hoB = (const ulonglong2*)&hown[(4 * s) * HH];
                        const ulonglong2* hpB = (const ulonglong2*)&hpv[(4 * s) * HH];
#pragma unroll
                        for (int j = 0; j < 25; j++) {
                            ulonglong2 wi = wip[j];
#pragma unroll
                            for (int r = 0; r < 4; r++) {
                                ulonglong2 ho = hoB[r * 25 + j];
                                ulonglong2 hp = hpB[r * 25 + j];
                                FMA2(a[r], w2[2 * j],     ho.x, a[r]);
                                FMA2(b[r], w2[2 * j + 1], ho.y, b[r]);
                                FMA2(a[r], wi.x, hp.x, a[r]);
                                FMA2(b[r], wi.y, hp.y, b[r]);
                            }
                        }
#pragma unroll
                        for (int r = 0; r < 4; r++) {
                            float p0, p1, q0, q1;
                            UNPACK2(p0, p1, a[r]); UNPACK2(q0, q1, b[r]);
                            gsh[(4 * s + r) * G4 + tid] = (p0 + p1) + (q0 + q1);
                        }
                    }
                } else {
                    for (int s = 0; s < nswp; s++) {
                        ull a[4], b[4];
#pragma unroll
                        for (int r = 0; r < 4; r++) { PACK2(a[r], bg, 0.f); PACK2(b[r], 0.f, 0.f); }
                        const ulonglong2* hoB = (const ulonglong2*)&hown[(4 * s) * HH];
#pragma unroll
                        for (int j = 0; j < 25; j++) {
#pragma unroll
                            for (int r = 0; r < 4; r++) {
                                ulonglong2 ho = hoB[r * 25 + j];
                                FMA2(a[r], w2[2 * j],     ho.x, a[r]);
                                FMA2(b[r], w2[2 * j + 1], ho.y, b[r]);
                            }
                        }
#pragma unroll
                        for (int r = 0; r < 4; r++) {
                            const float* xp = &hpv[(4 * s + r) * 5];
                            float sB = w0[0] * xp[0] + w0[1] * xp[1] + w0[2] * xp[2]
                                     + w0[3] * xp[3] + w0[4] * xp[4];
                            float p0, p1, q0, q1;
                            UNPACK2(p0, p1, a[r]); UNPACK2(q0, q1, b[r]);
                            gsh[(4 * s + r) * G4 + tid] = (p0 + p1) + (q0 + q1) + sB;
                        }
                    }
                }
            }
            __syncthreads();                                     // B2

            // activation + state update + publish h
#pragma unroll
            for (int q = 0; q < 4; q++) {
                int u = tid + q * 416;
                if (u < nr * HH) {
                    int r = u / HH, n = u - r * HH;
                    const float* gp = &gsh[r * G4 + n];
                    float iv = sigf(gp[0]);
                    float fv = sigf(gp[100]);
                    float gv = tanh_(gp[200]);
                    float ov = sigf(gp[300]);
                    cst[q] = fv * cst[q] + iv * gv;
                    float hv = ov * tanh_(cst[q]);
                    hown[r * HH + n] = hv;
                    if (layer < 4)
                        hdstB[(size_t)r * Tlen * HH + (size_t)t * HH + n] = hv;
                    else if (t == Tlen - 1)
                        g_hLast[(row0 + r) * HH + n] = hv;
                }
            }
            // no barrier here: next iteration's B1 separates hown/gsh reuse
        }

        // publish chunk: all threads fence, bar, one thread release-stores
        if (layer < 4) {
            __threadfence();
            __syncthreads();
            if (tid == 0) flag_release(&g_flag[layer][pb], fbase + (unsigned)ck + 1u);
        }
    }
}

// ---------------------------------------------------------------------------
// BN (eval) + 3-layer MLP head
// ---------------------------------------------------------------------------
__global__ void head_kernel(const float* __restrict__ gamma,
                            const float* __restrict__ beta,
                            const float* __restrict__ rmean,
                            const float* __restrict__ rvar,
                            const float* __restrict__ W1, const float* __restrict__ b1,
                            const float* __restrict__ W2, const float* __restrict__ b2,
                            const float* __restrict__ W3, const float* __restrict__ b3,
                            float* __restrict__ out)
{
    __shared__ float xa[HH], ya[HH];
    int b = blockIdx.x, tid = threadIdx.x;

    if (tid < HH) {
        float v = g_hLast[b * HH + tid];
        xa[tid] = (v - rmean[tid]) * rsqrtf(rvar[tid] + 1e-5f) * gamma[tid] + beta[tid];
    }
    __syncthreads();
    if (tid < HH) {
        float a = b1[tid];
#pragma unroll 4
        for (int k = 0; k < HH; k++) a += xa[k] * W1[(size_t)tid * HH + k];
        ya[tid] = fmaxf(a, 0.0f);
    }
    __syncthreads();
    if (tid < HH) {
        float a = b2[tid];
#pragma unroll 4
        for (int k = 0; k < HH; k++) a += ya[k] * W2[(size_t)tid * HH + k];
        xa[tid] = fmaxf(a, 0.0f);
    }
    __syncthreads();
    if (tid < Oout) {
        float a = b3[tid];
#pragma unroll 4
        for (int k = 0; k < HH; k++) a += xa[k] * W3[(size_t)tid * HH + k];
        out[(size_t)b * Oout + tid] = a;
    }
}

// ---------------------------------------------------------------------------
// kernel_launch
// ---------------------------------------------------------------------------
extern "C" void kernel_launch(void* const* d_in, const int* in_sizes, int n_in,
                              void* d_out, int out_size)
{
    const float* x     = (const float*)d_in[0];
    const float* W_ih0 = (const float*)d_in[1];
    const float* W_hh0 = (const float*)d_in[2];
    const float* b0    = (const float*)d_in[3];
    const float* W_ih  = (const float*)d_in[4];
    const float* W_hh  = (const float*)d_in[5];
    const float* bb    = (const float*)d_in[6];
    const float* gamma = (const float*)d_in[7];
    const float* beta  = (const float*)d_in[8];
    const float* rmean = (const float*)d_in[9];
    const float* rvar  = (const float*)d_in[10];
    const float* W1    = (const float*)d_in[11];
    const float* b1    = (const float*)d_in[12];
    const float* W2    = (const float*)d_in[13];
    const float* b2    = (const float*)d_in[14];
    const float* W3    = (const float*)d_in[15];
    const float* b3    = (const float*)d_in[16];
    float* out = (float*)d_out;

    static int smem_set = 0;
    if (!smem_set) {
        cudaFuncSetAttribute((const void*)lstm_wave,
                             cudaFuncAttributeMaxDynamicSharedMemorySize, SMEM_BYTES);
        smem_set = 1;
    }

    lstm_wave<<<144, 416, SMEM_BYTES>>>(x, W_ih0, W_hh0, b0, W_ih, W_hh, bb);
    head_kernel<<<Bsz, 128>>>(gamma, beta, rmean, rvar,
                              W1, b1, W2, b2, W3, b3, out);
}

// round 5
// speedup vs baseline: 3.1488x; 3.1488x over previous
#include <cuda_runtime.h>
#include <cstdint>

#define Bsz 256
#define Tlen 512
#define Iin 5
#define HH 100
#define G4 400
#define NL 5
#define Oout 3
#define BT (Bsz*Tlen)

typedef unsigned long long ull;

#define FMA2(d, a, b, c) asm("fma.rn.f32x2 %0, %1, %2, %3;" : "=l"(d) : "l"(a), "l"(b), "l"(c))
#define PACK2(d, lo, hi) asm("mov.b64 %0, {%1, %2};" : "=l"(d) : "f"(lo), "f"(hi))
#define UNPACK2(lo, hi, v) asm("mov.b64 {%0, %1}, %2;" : "=f"(lo), "=f"(hi) : "l"(v))

// ---------------------------------------------------------------------------
// Scratch
// ---------------------------------------------------------------------------
__device__ float g_gates[(size_t)BT * G4];
__device__ float g_hA[(size_t)BT * HH];
__device__ float g_hB[(size_t)BT * HH];

__device__ __forceinline__ float sigf(float x) {
    return __fdividef(1.0f, 1.0f + __expf(-x));
}
__device__ __forceinline__ float tanh_(float x) {
    return __fdividef(2.0f, 1.0f + __expf(-2.0f * x)) - 1.0f;
}

// ---------------------------------------------------------------------------
// Kernel 1a: layer-0 input projection (K=5)
// ---------------------------------------------------------------------------
__global__ void gemm_in0(const float* __restrict__ x,
                         const float* __restrict__ Wih,
                         const float* __restrict__ bias)
{
    int idx = blockIdx.x * blockDim.x + threadIdx.x;
    int m = idx / G4;
    int n = idx - m * G4;
    const float* xr = x + (size_t)m * Iin;
    const float* wr = Wih + (size_t)n * Iin;
    float a = bias[n];
#pragma unroll
    for (int k = 0; k < Iin; k++) a += xr[k] * wr[k];
    g_gates[(size_t)idx] = a;
}

// ---------------------------------------------------------------------------
// Kernel 1b: layers 1..4 input projection, f32x2-packed SGEMM (round-2 proven)
// ---------------------------------------------------------------------------
#define GM 64
#define GNJ 7
#define GN (16*GNJ)
#define KP 102
#define GEMM_SMEM ((GM + GN) * KP * 4)

__global__ __launch_bounds__(256)
void gemm_in(int inSel,
             const float* __restrict__ W,
             const float* __restrict__ bias)
{
    extern __shared__ float sm[];
    float* Xs = sm;
    float* Ws = sm + GM * KP;

    const float* X = inSel ? g_hB : g_hA;
    int tid = threadIdx.x;
    int tx = tid & 15;
    int ty = (tid >> 4) & 15;
    size_t m0 = (size_t)blockIdx.x * GM;
    int n0 = blockIdx.y * GN;

    {
        const float2* Xg = (const float2*)(X + m0 * 100);
        for (int idx = tid; idx < GM * 50; idx += 256) {
            int r = idx / 50, c = idx - r * 50;
            float2 v = Xg[(size_t)r * 50 + c];
            *(float2*)&Xs[r * KP + 2 * c] = v;
        }
        const float2* Wg = (const float2*)W;
        for (int idx = tid; idx < GN * 50; idx += 256) {
            int r = idx / 50, c = idx - r * 50;
            int gn = n0 + r;
            float2 v = (gn < G4) ? Wg[(size_t)gn * 50 + c] : make_float2(0.f, 0.f);
            *(float2*)&Ws[r * KP + 2 * c] = v;
        }
    }
    __syncthreads();

    ull acc[4][GNJ];
#pragma unroll
    for (int i = 0; i < 4; i++)
#pragma unroll
        for (int j = 0; j < GNJ; j++) PACK2(acc[i][j], 0.f, 0.f);

    const ull* xrow[4];
#pragma unroll
    for (int i = 0; i < 4; i++) xrow[i] = (const ull*)&Xs[(ty + 16 * i) * KP];
    const ull* wrow[GNJ];
#pragma unroll
    for (int j = 0; j < GNJ; j++) wrow[j] = (const ull*)&Ws[(tx + 16 * j) * KP];

#pragma unroll 5
    for (int k = 0; k < 50; k++) {
        ull dx[4], dw[GNJ];
#pragma unroll
        for (int i = 0; i < 4; i++) dx[i] = xrow[i][k];
#pragma unroll
        for (int j = 0; j < GNJ; j++) dw[j] = wrow[j][k];
#pragma unroll
        for (int i = 0; i < 4; i++)
#pragma unroll
            for (int j = 0; j < GNJ; j++)
                FMA2(acc[i][j], dx[i], dw[j], acc[i][j]);
    }

#pragma unroll
    for (int i = 0; i < 4; i++) {
        size_t m = m0 + ty + 16 * i;
#pragma unroll
        for (int j = 0; j < GNJ; j++) {
            int n = n0 + tx + 16 * j;
            if (n < G4) {
                float lo, hi;
                UNPACK2(lo, hi, acc[i][j]);
                g_gates[m * G4 + n] = lo + hi + bias[n];
            }
        }
    }
}

// ---------------------------------------------------------------------------
// Kernel 2: LSTM recurrence, quad-gate layout.
// 128 blocks x 2 batch rows x 400 threads. Thread 4u+s owns gate s of unit u
// (gate row s*100+u), weights in 50 packed regs. After the dot the 4 gate
// values of unit u sit in adjacent lanes -> 3 shfl pulls into lane s=0 which
// updates c,h. h double-buffered in smem (parity by t) -> ONE barrier/step.
// ---------------------------------------------------------------------------
__global__ __launch_bounds__(400, 1)
void lstm_rec(const float* __restrict__ W_hh,   // [400,100]
              int outSel, int storeAll)
{
    __shared__ __align__(16) float hbuf[2][2][104];  // [parity][row][unit]

    const int tid = threadIdx.x;
    const int u = tid >> 2;          // unit 0..99
    const int s = tid & 3;           // 0=i 1=f 2=g 3=o
    const int grow = s * 100 + u;    // gate row
    const int b0 = blockIdx.x * 2;
    const unsigned mask = (tid >= 384) ? 0x0000FFFFu : 0xFFFFFFFFu;
    const int lbase = (tid & 31) & ~3;   // quad base lane

    // weights -> registers, k-pair packed
    ull w2[50];
    {
        const float4* wr = (const float4*)(W_hh + (size_t)grow * HH);
#pragma unroll
        for (int j = 0; j < 25; j++) {
            float4 v = wr[j];
            PACK2(w2[2 * j],     v.x, v.y);
            PACK2(w2[2 * j + 1], v.z, v.w);
        }
    }

    // init h parity-0 buffers
    if (tid < 104) { hbuf[0][0][tid] = 0.f; hbuf[0][1][tid] = 0.f; }
    float c0 = 0.f, c1 = 0.f;        // live only in s==0 lanes

    const float* gp0 = g_gates + (size_t)b0 * Tlen * G4;
    const float* gp1 = gp0 + (size_t)Tlen * G4;
    float* hout = outSel ? g_hB : g_hA;
    float* hs0 = hout + (size_t)b0 * Tlen * HH;
    float* hs1 = hs0 + (size_t)Tlen * HH;

    float pg0 = gp0[grow];
    float pg1 = gp1[grow];
    __syncthreads();

    for (int t = 0; t < Tlen; t++) {
        const int p = t & 1;

        // dot: gate = preact + Whh[grow] . h(row)
        ull a0, a1, e0, e1;
        PACK2(a0, pg0, 0.f); PACK2(a1, 0.f, 0.f);
        PACK2(e0, pg1, 0.f); PACK2(e1, 0.f, 0.f);
        {
            const ulonglong2* hA = (const ulonglong2*)hbuf[p][0];
            const ulonglong2* hB = (const ulonglong2*)hbuf[p][1];
#pragma unroll
            for (int j = 0; j < 25; j++) {
                ulonglong2 vA = hA[j];
                ulonglong2 vB = hB[j];
                FMA2(a0, w2[2 * j],     vA.x, a0);
                FMA2(a1, w2[2 * j + 1], vA.y, a1);
                FMA2(e0, w2[2 * j],     vB.x, e0);
                FMA2(e1, w2[2 * j + 1], vB.y, e1);
            }
        }
        // prefetch next step's pre-activations
        {
            int tn = (t + 1 < Tlen) ? (t + 1) : t;
            pg0 = gp0[(size_t)tn * G4 + grow];
            pg1 = gp1[(size_t)tn * G4 + grow];
        }
        float q0, q1, q2, q3;
        UNPACK2(q0, q1, a0); UNPACK2(q2, q3, a1);
        float gv0 = (q0 + q1) + (q2 + q3);
        UNPACK2(q0, q1, e0); UNPACK2(q2, q3, e1);
        float gv1 = (q0 + q1) + (q2 + q3);

        // own-gate activation (g-gate: tanh; others: sigmoid)
        float v0 = (s == 2) ? tanh_(gv0) : sigf(gv0);
        float v1 = (s == 2) ? tanh_(gv1) : sigf(gv1);

        // pull f,g,o into lane s==0 (i already local there)
        float f0 = __shfl_sync(mask, v0, lbase + 1);
        float g0 = __shfl_sync(mask, v0, lbase + 2);
        float o0 = __shfl_sync(mask, v0, lbase + 3);
        float f1 = __shfl_sync(mask, v1, lbase + 1);
        float g1 = __shfl_sync(mask, v1, lbase + 2);
        float o1 = __shfl_sync(mask, v1, lbase + 3);

        const int pn = p ^ 1;
        if (s == 0) {
            c0 = f0 * c0 + v0 * g0;
            float h0 = o0 * tanh_(c0);
            c1 = f1 * c1 + v1 * g1;
            float h1 = o1 * tanh_(c1);
            hbuf[pn][0][u] = h0;
            hbuf[pn][1][u] = h1;
            if (storeAll || t == Tlen - 1) {
                hs0[(size_t)t * HH + u] = h0;
                hs1[(size_t)t * HH + u] = h1;
            }
        }
        __syncthreads();
    }
}

// ---------------------------------------------------------------------------
// Kernel 3: BN + MLP head
// ---------------------------------------------------------------------------
__global__ void head_kernel(int inSel,
                            const float* __restrict__ gamma,
                            const float* __restrict__ beta,
                            const float* __restrict__ rmean,
                            const float* __restrict__ rvar,
                            const float* __restrict__ W1, const float* __restrict__ b1,
                            const float* __restrict__ W2, const float* __restrict__ b2,
                            const float* __restrict__ W3, const float* __restrict__ b3,
                            float* __restrict__ out)
{
    __shared__ float xa[HH], ya[HH];
    const float* hseq = inSel ? g_hB : g_hA;
    int b = blockIdx.x, tid = threadIdx.x;

    if (tid < HH) {
        float v = hseq[((size_t)b * Tlen + (Tlen - 1)) * HH + tid];
        xa[tid] = (v - rmean[tid]) * rsqrtf(rvar[tid] + 1e-5f) * gamma[tid] + beta[tid];
    }
    __syncthreads();
    if (tid < HH) {
        float a = b1[tid];
#pragma unroll 4
        for (int k = 0; k < HH; k++) a += xa[k] * W1[(size_t)tid * HH + k];
        ya[tid] = fmaxf(a, 0.0f);
    }
    __syncthreads();
    if (tid < HH) {
        float a = b2[tid];
#pragma unroll 4
        for (int k = 0; k < HH; k++) a += ya[k] * W2[(size_t)tid * HH + k];
        xa[tid] = fmaxf(a, 0.0f);
    }
    __syncthreads();
    if (tid < Oout) {
        float a = b3[tid];
#pragma unroll 4
        for (int k = 0; k < HH; k++) a += xa[k] * W3[(size_t)tid * HH + k];
        out[(size_t)b * Oout + tid] = a;
    }
}

// ---------------------------------------------------------------------------
// kernel_launch
// ---------------------------------------------------------------------------
extern "C" void kernel_launch(void* const* d_in, const int* in_sizes, int n_in,
                              void* d_out, int out_size)
{
    const float* x     = (const float*)d_in[0];
    const float* W_ih0 = (const float*)d_in[1];
    const float* W_hh0 = (const float*)d_in[2];
    const float* b0    = (const float*)d_in[3];
    const float* W_ih  = (const float*)d_in[4];
    const float* W_hh  = (const float*)d_in[5];
    const float* bb    = (const float*)d_in[6];
    const float* gamma = (const float*)d_in[7];
    const float* beta  = (const float*)d_in[8];
    const float* rmean = (const float*)d_in[9];
    const float* rvar  = (const float*)d_in[10];
    const float* W1    = (const float*)d_in[11];
    const float* b1    = (const float*)d_in[12];
    const float* W2    = (const float*)d_in[13];
    const float* b2    = (const float*)d_in[14];
    const float* W3    = (const float*)d_in[15];
    const float* b3    = (const float*)d_in[16];
    float* out = (float*)d_out;

    static int smem_set = 0;
    if (!smem_set) {
        cudaFuncSetAttribute((const void*)gemm_in,
                             cudaFuncAttributeMaxDynamicSharedMemorySize, GEMM_SMEM);
        smem_set = 1;
    }

    gemm_in0<<<(BT * G4) / 256, 256>>>(x, W_ih0, b0);
    lstm_rec<<<128, 400>>>(W_hh0, 0, 1);

    dim3 ggrid(BT / GM, 4);
    for (int l = 0; l < NL - 1; l++) {
        int inSel  = (l % 2 == 0) ? 0 : 1;
        int outSel = 1 - inSel;
        gemm_in<<<ggrid, 256, GEMM_SMEM>>>(inSel, W_ih + (size_t)l * G4 * HH,
                                           bb + (size_t)l * G4);
        lstm_rec<<<128, 400>>>(W_hh + (size_t)l * G4 * HH, outSel,
                               (l == NL - 2) ? 0 : 1);
    }

    head_kernel<<<Bsz, 128>>>(0, gamma, beta, rmean, rvar,
                              W1, b1, W2, b2, W3, b3, out);
}

// round 6
// speedup vs baseline: 3.3870x; 1.0756x over previous
#include <cuda_runtime.h>
#include <cstdint>

#define Bsz 256
#define Tlen 512
#define Iin 5
#define HH 100
#define G4 400
#define NL 5
#define Oout 3
#define BT (Bsz*Tlen)

typedef unsigned long long ull;

#define FMA2(d, a, b, c) asm("fma.rn.f32x2 %0, %1, %2, %3;" : "=l"(d) : "l"(a), "l"(b), "l"(c))
#define PACK2(d, lo, hi) asm("mov.b64 %0, {%1, %2};" : "=l"(d) : "f"(lo), "f"(hi))
#define UNPACK2(lo, hi, v) asm("mov.b64 {%0, %1}, %2;" : "=f"(lo), "=f"(hi) : "l"(v))

// ---------------------------------------------------------------------------
// Scratch
// ---------------------------------------------------------------------------
__device__ float g_gates[(size_t)BT * G4];
__device__ float g_hA[(size_t)BT * HH];
__device__ float g_hB[(size_t)BT * HH];

__device__ __forceinline__ float sigf(float x) {
    return __fdividef(1.0f, 1.0f + __expf(-x));
}
__device__ __forceinline__ float tanh_(float x) {
    return __fdividef(2.0f, 1.0f + __expf(-2.0f * x)) - 1.0f;
}

// ---------------------------------------------------------------------------
// Kernel 1a: layer-0 input projection (K=5)
// ---------------------------------------------------------------------------
__global__ void gemm_in0(const float* __restrict__ x,
                         const float* __restrict__ Wih,
                         const float* __restrict__ bias)
{
    int idx = blockIdx.x * blockDim.x + threadIdx.x;
    int m = idx / G4;
    int n = idx - m * G4;
    const float* xr = x + (size_t)m * Iin;
    const float* wr = Wih + (size_t)n * Iin;
    float a = bias[n];
#pragma unroll
    for (int k = 0; k < Iin; k++) a += xr[k] * wr[k];
    g_gates[(size_t)idx] = a;
}

// ---------------------------------------------------------------------------
// Kernel 1b: layers 1..4 input projection, f32x2-packed SGEMM (proven)
// ---------------------------------------------------------------------------
#define GM 64
#define GNJ 7
#define GN (16*GNJ)
#define KP 102
#define GEMM_SMEM ((GM + GN) * KP * 4)

__global__ __launch_bounds__(256)
void gemm_in(int inSel,
             const float* __restrict__ W,
             const float* __restrict__ bias)
{
    extern __shared__ float sm[];
    float* Xs = sm;
    float* Ws = sm + GM * KP;

    const float* X = inSel ? g_hB : g_hA;
    int tid = threadIdx.x;
    int tx = tid & 15;
    int ty = (tid >> 4) & 15;
    size_t m0 = (size_t)blockIdx.x * GM;
    int n0 = blockIdx.y * GN;

    {
        const float2* Xg = (const float2*)(X + m0 * 100);
        for (int idx = tid; idx < GM * 50; idx += 256) {
            int r = idx / 50, c = idx - r * 50;
            float2 v = Xg[(size_t)r * 50 + c];
            *(float2*)&Xs[r * KP + 2 * c] = v;
        }
        const float2* Wg = (const float2*)W;
        for (int idx = tid; idx < GN * 50; idx += 256) {
            int r = idx / 50, c = idx - r * 50;
            int gn = n0 + r;
            float2 v = (gn < G4) ? Wg[(size_t)gn * 50 + c] : make_float2(0.f, 0.f);
            *(float2*)&Ws[r * KP + 2 * c] = v;
        }
    }
    __syncthreads();

    ull acc[4][GNJ];
#pragma unroll
    for (int i = 0; i < 4; i++)
#pragma unroll
        for (int j = 0; j < GNJ; j++) PACK2(acc[i][j], 0.f, 0.f);

    const ull* xrow[4];
#pragma unroll
    for (int i = 0; i < 4; i++) xrow[i] = (const ull*)&Xs[(ty + 16 * i) * KP];
    const ull* wrow[GNJ];
#pragma unroll
    for (int j = 0; j < GNJ; j++) wrow[j] = (const ull*)&Ws[(tx + 16 * j) * KP];

#pragma unroll 5
    for (int k = 0; k < 50; k++) {
        ull dx[4], dw[GNJ];
#pragma unroll
        for (int i = 0; i < 4; i++) dx[i] = xrow[i][k];
#pragma unroll
        for (int j = 0; j < GNJ; j++) dw[j] = wrow[j][k];
#pragma unroll
        for (int i = 0; i < 4; i++)
#pragma unroll
            for (int j = 0; j < GNJ; j++)
                FMA2(acc[i][j], dx[i], dw[j], acc[i][j]);
    }

#pragma unroll
    for (int i = 0; i < 4; i++) {
        size_t m = m0 + ty + 16 * i;
#pragma unroll
        for (int j = 0; j < GNJ; j++) {
            int n = n0 + tx + 16 * j;
            if (n < G4) {
                float lo, hi;
                UNPACK2(lo, hi, acc[i][j]);
                g_gates[m * G4 + n] = lo + hi + bias[n];
            }
        }
    }
}

// ---------------------------------------------------------------------------
// Kernel 2: LSTM recurrence, split-K quad-gate layout.
// 128 blocks x 2 batch rows x 800 threads (25 warps).
// Thread u*8 + s*2 + half owns HALF of gate row (s*100+u): 13 16B K-chunks
// starting at chunk 13*half (chunk 25 is a zero-weight dummy so both halves
// run identical unrolled loops). Partials combine via shfl_xor(1); gate
// quad (i,f,g,o) sits in lanes lb..lb+7, gathered by lane lb (s=0,half=0)
// which owns c and h. h double-buffered in smem; ONE barrier per step.
// ---------------------------------------------------------------------------
__global__ __launch_bounds__(800, 1)
void lstm_rec(const float* __restrict__ W_hh,   // [400,100]
              int outSel, int storeAll)
{
    __shared__ __align__(16) float hbuf[2][2][104];  // [parity][row][unit(+pad)]

    const int tid  = threadIdx.x;
    const int u    = tid >> 3;          // unit 0..99
    const int s    = (tid >> 1) & 3;    // gate 0=i 1=f 2=g 3=o
    const int half = tid & 1;           // K half
    const int grow = s * 100 + u;
    const int b0   = blockIdx.x * 2;
    const int lane = tid & 31;
    const int lb   = lane & ~7;         // unit-octet base lane
    const int cbase = 13 * half;        // first 16B chunk

    // half of the weight row -> 26 packed regs (chunk 25 = zeros)
    ull w2[26];
    {
        const float4* wr = (const float4*)(W_hh + (size_t)grow * HH);
#pragma unroll
        for (int i = 0; i < 13; i++) {
            int cc = cbase + i;
            float4 v = (cc < 25) ? wr[cc] : make_float4(0.f, 0.f, 0.f, 0.f);
            PACK2(w2[2 * i],     v.x, v.y);
            PACK2(w2[2 * i + 1], v.z, v.w);
        }
    }

    // zero ALL of hbuf (including padding floats 100..103 of both parities:
    // the dummy chunk reads them, zero weights * zero data stays clean)
    if (tid < 416) ((float*)hbuf)[tid] = 0.f;
    float c0 = 0.f, c1 = 0.f;           // live in (s==0 && half==0) lanes

    const float* gp0 = g_gates + (size_t)b0 * Tlen * G4;
    const float* gp1 = gp0 + (size_t)Tlen * G4;
    float* hout = outSel ? g_hB : g_hA;
    float* hs0 = hout + (size_t)b0 * Tlen * HH;
    float* hs1 = hs0 + (size_t)Tlen * HH;

    float pg0 = gp0[grow];
    float pg1 = gp1[grow];
    __syncthreads();

    for (int t = 0; t < Tlen; t++) {
        const int p = t & 1;
        const float cur0 = (half == 0) ? pg0 : 0.f;   // add preact once per pair
        const float cur1 = (half == 0) ? pg1 : 0.f;

        ull a0, a1, e0, e1;
        PACK2(a0, cur0, 0.f); PACK2(a1, 0.f, 0.f);
        PACK2(e0, cur1, 0.f); PACK2(e1, 0.f, 0.f);
        {
            const ulonglong2* hA = (const ulonglong2*)hbuf[p][0];
            const ulonglong2* hB = (const ulonglong2*)hbuf[p][1];
#pragma unroll
            for (int i = 0; i < 13; i++) {
                ulonglong2 vA = hA[cbase + i];
                ulonglong2 vB = hB[cbase + i];
                FMA2(a0, w2[2 * i],     vA.x, a0);
                FMA2(a1, w2[2 * i + 1], vA.y, a1);
                FMA2(e0, w2[2 * i],     vB.x, e0);
                FMA2(e1, w2[2 * i + 1], vB.y, e1);
            }
        }
        // prefetch next step's pre-activations
        {
            int tn = (t + 1 < Tlen) ? (t + 1) : t;
            pg0 = gp0[(size_t)tn * G4 + grow];
            pg1 = gp1[(size_t)tn * G4 + grow];
        }
        float q0, q1, q2, q3;
        UNPACK2(q0, q1, a0); UNPACK2(q2, q3, a1);
        float part0 = (q0 + q1) + (q2 + q3);
        UNPACK2(q0, q1, e0); UNPACK2(q2, q3, e1);
        float part1 = (q0 + q1) + (q2 + q3);

        // combine K halves (partner = adjacent lane)
        float full0 = part0 + __shfl_xor_sync(0xFFFFFFFFu, part0, 1);
        float full1 = part1 + __shfl_xor_sync(0xFFFFFFFFu, part1, 1);

        // own-gate activation (redundant in both halves; keeps lanes converged)
        float v0 = (s == 2) ? tanh_(full0) : sigf(full0);
        float v1 = (s == 2) ? tanh_(full1) : sigf(full1);

        // gather f,g,o into the octet-base lane (i is local there)
        float f0 = __shfl_sync(0xFFFFFFFFu, v0, lb + 2);
        float g0 = __shfl_sync(0xFFFFFFFFu, v0, lb + 4);
        float o0 = __shfl_sync(0xFFFFFFFFu, v0, lb + 6);
        float f1 = __shfl_sync(0xFFFFFFFFu, v1, lb + 2);
        float g1 = __shfl_sync(0xFFFFFFFFu, v1, lb + 4);
        float o1 = __shfl_sync(0xFFFFFFFFu, v1, lb + 6);

        const int pn = p ^ 1;
        if ((tid & 7) == 0) {           // s==0 && half==0
            c0 = f0 * c0 + v0 * g0;
            float h0 = o0 * tanh_(c0);
            c1 = f1 * c1 + v1 * g1;
            float h1 = o1 * tanh_(c1);
            hbuf[pn][0][u] = h0;
            hbuf[pn][1][u] = h1;
            if (storeAll || t == Tlen - 1) {
                hs0[(size_t)t * HH + u] = h0;
                hs1[(size_t)t * HH + u] = h1;
            }
        }
        __syncthreads();
    }
}

// ---------------------------------------------------------------------------
// Kernel 3: BN + MLP head
// ---------------------------------------------------------------------------
__global__ void head_kernel(int inSel,
                            const float* __restrict__ gamma,
                            const float* __restrict__ beta,
                            const float* __restrict__ rmean,
                            const float* __restrict__ rvar,
                            const float* __restrict__ W1, const float* __restrict__ b1,
                            const float* __restrict__ W2, const float* __restrict__ b2,
                            const float* __restrict__ W3, const float* __restrict__ b3,
                            float* __restrict__ out)
{
    __shared__ float xa[HH], ya[HH];
    const float* hseq = inSel ? g_hB : g_hA;
    int b = blockIdx.x, tid = threadIdx.x;

    if (tid < HH) {
        float v = hseq[((size_t)b * Tlen + (Tlen - 1)) * HH + tid];
        xa[tid] = (v - rmean[tid]) * rsqrtf(rvar[tid] + 1e-5f) * gamma[tid] + beta[tid];
    }
    __syncthreads();
    if (tid < HH) {
        float a = b1[tid];
#pragma unroll 4
        for (int k = 0; k < HH; k++) a += xa[k] * W1[(size_t)tid * HH + k];
        ya[tid] = fmaxf(a, 0.0f);
    }
    __syncthreads();
    if (tid < HH) {
        float a = b2[tid];
#pragma unroll 4
        for (int k = 0; k < HH; k++) a += ya[k] * W2[(size_t)tid * HH + k];
        xa[tid] = fmaxf(a, 0.0f);
    }
    __syncthreads();
    if (tid < Oout) {
        float a = b3[tid];
#pragma unroll 4
        for (int k = 0; k < HH; k++) a += xa[k] * W3[(size_t)tid * HH + k];
        out[(size_t)b * Oout + tid] = a;
    }
}

// ---------------------------------------------------------------------------
// kernel_launch
// ---------------------------------------------------------------------------
extern "C" void kernel_launch(void* const* d_in, const int* in_sizes, int n_in,
                              void* d_out, int out_size)
{
    const float* x     = (const float*)d_in[0];
    const float* W_ih0 = (const float*)d_in[1];
    const float* W_hh0 = (const float*)d_in[2];
    const float* b0    = (const float*)d_in[3];
    const float* W_ih  = (const float*)d_in[4];
    const float* W_hh  = (const float*)d_in[5];
    const float* bb    = (const float*)d_in[6];
    const float* gamma = (const float*)d_in[7];
    const float* beta  = (const float*)d_in[8];
    const float* rmean = (const float*)d_in[9];
    const float* rvar  = (const float*)d_in[10];
    const float* W1    = (const float*)d_in[11];
    const float* b1    = (const float*)d_in[12];
    const float* W2    = (const float*)d_in[13];
    const float* b2    = (const float*)d_in[14];
    const float* W3    = (const float*)d_in[15];
    const float* b3    = (const float*)d_in[16];
    float* out = (float*)d_out;

    static int smem_set = 0;
    if (!smem_set) {
        cudaFuncSetAttribute((const void*)gemm_in,
                             cudaFuncAttributeMaxDynamicSharedMemorySize, GEMM_SMEM);
        smem_set = 1;
    }

    gemm_in0<<<(BT * G4) / 256, 256>>>(x, W_ih0, b0);
    lstm_rec<<<128, 800>>>(W_hh0, 0, 1);

    dim3 ggrid(BT / GM, 4);
    for (int l = 0; l < NL - 1; l++) {
        int inSel  = (l % 2 == 0) ? 0 : 1;
        int outSel = 1 - inSel;
        gemm_in<<<ggrid, 256, GEMM_SMEM>>>(inSel, W_ih + (size_t)l * G4 * HH,
                                           bb + (size_t)l * G4);
        lstm_rec<<<128, 800>>>(W_hh + (size_t)l * G4 * HH, outSel,
                               (l == NL - 2) ? 0 : 1);
    }

    head_kernel<<<Bsz, 128>>>(0, gamma, beta, rmean, rvar,
                              W1, b1, W2, b2, W3, b3, out);
}